// round 12
// baseline (speedup 1.0000x reference)
#include <cuda_runtime.h>

static constexpr int C = 512;
static constexpr int B = 8;
static constexpr int TOPK = 256;            // C * (1 - EXCHANGE_RATIO)
static constexpr unsigned ROWS = 8192;      // 2 * B * C input channel rows
static constexpr int NRANK = 32;            // mask blocks (16 per array)

// g_mask[a][w]: bit (c&31) of word w=c>>5 set <=> channel c is NON-top in
// |bn_a|. Written by the 32 mask blocks (one word each, plain store).
__device__ unsigned g_mask[2][16];
// Tables built by block 0 from the masks:
//   g_tp[a][c] = -1 if channel c is top in |bn_a|, else its position among
//                a's non-top channels (ascending index).
//   g_nt[a][k] = k-th non-top channel of array a (ascending index order).
__device__ int g_tp[2][C];
__device__ int g_nt[2][TOPK];
// Handshake (zero-initialized; reset by the last block each run).
__device__ int g_ready;   // mask words published (0..32)
__device__ int g_tab;     // tables published (0/1)
__device__ int g_done;

__global__ void __launch_bounds__(256)
exchange_fused_kernel(const float4* __restrict__ x1,
                      const float4* __restrict__ x2,
                      float4* __restrict__ out,
                      const float* __restrict__ bn1,
                      const float* __restrict__ bn2) {
    unsigned row = blockIdx.x;              // INPUT row: a*4096 + b*512 + c
    int t = threadIdx.x;

    // ─── Stage 1: blocks 0..31 each rank 32 channels, publish one mask word.
    // Block (aa*16 + j) covers channels [j*32, j*32+32) of bn_{aa}. ───
    if (row < NRANK) {
        __shared__ unsigned long long key[C];
        __shared__ unsigned wsh;

        int aa = (int)(row >> 4);
        int j  = (int)(row & 15u);
        const float* bn = aa ? bn2 : bn1;

        // Non-negative floats order like their bit patterns.
        // key = (bits << 10) | (1023 - c): equal values -> smaller index
        // ranks higher, matching jax.lax.top_k tie semantics.
        {
            unsigned b0 = __float_as_uint(fabsf(bn[t]));
            unsigned b1 = __float_as_uint(fabsf(bn[t + 256]));
            key[t]       = ((unsigned long long)b0 << 10) | (unsigned)(1023 - t);
            key[t + 256] = ((unsigned long long)b1 << 10) | (unsigned)(1023 - (t + 256));
        }
        if (t == 0) wsh = 0u;
        __syncthreads();

        // Thread t: channel ch = j*32 + (t>>3); lane-part (t&7) scans keys
        // part + 8*i as ulonglong2 (conflict-free interleaved LDS).
        int ch   = (j << 5) + (t >> 3);
        int part = t & 7;
        unsigned long long k = key[ch];
        int r = 0;
        const ulonglong2* k2 = (const ulonglong2*)key;
        #pragma unroll 8
        for (int i = 0; i < 32; ++i) {
            ulonglong2 v = k2[part + (i << 3)];
            r += (v.x > k) + (v.y > k);
        }
        r += __shfl_down_sync(0xFFFFFFFFu, r, 4, 8);
        r += __shfl_down_sync(0xFFFFFFFFu, r, 2, 8);
        r += __shfl_down_sync(0xFFFFFFFFu, r, 1, 8);
        if (part == 0 && r >= TOPK)
            atomicOr(&wsh, 1u << (ch & 31));
        __syncthreads();

        if (t == 0) {
            g_mask[aa][j] = wsh;            // block owns this word
            __threadfence();                // publish before count
            atomicAdd(&g_ready, 1);
        }

        // ─── Stage 2: block 0 converts masks -> tables. ───
        if (row == 0) {
            if (t == 0) {
                while (*(volatile int*)&g_ready != NRANK) __nanosleep(32);
                __threadfence();            // acquire masks
            }
            __syncthreads();

            #pragma unroll
            for (int aa2 = 0; aa2 < 2; ++aa2) {
                #pragma unroll
                for (int h = 0; h < 2; ++h) {
                    int ch2 = t + (h << 8);
                    int w = ch2 >> 5, bit = ch2 & 31;
                    unsigned m = g_mask[aa2][w];
                    int p = __popc(m & ((1u << bit) - 1u));
                    for (int w2 = 0; w2 < w; ++w2)
                        p += __popc(g_mask[aa2][w2]);
                    bool nt = (m >> bit) & 1u;
                    g_tp[aa2][ch2] = nt ? p : -1;
                    if (nt) g_nt[aa2][p] = ch2;
                }
            }
            __syncthreads();
            if (t == 0) {
                __threadfence();            // publish tables before flag
                *(volatile int*)&g_tab = 1;
            }
        }
    }

    // ─── Wait for tables. Later-wave blocks see the flag already set. ───
    if (t == 0) {
        while (*(volatile int*)&g_tab != 1) __nanosleep(32);
        __threadfence();                    // acquire
    }
    __syncthreads();

    // ─── Lean copy body (R2 structure): resolve dest, then 4x load/store. ───
    unsigned c = row & 511u;
    unsigned a = row >> 12;                 // source array
    unsigned b = (row >> 9) & 7u;

    // x_a[:,c,:] -> y_a[:,c,:] if c is top in bn_a, else
    // -> y_{a^1}[:, nt_{a^1}[pos_a(c)], :] (order-aligned exchange).
    int tp = g_tp[a][c];
    unsigned dw, dc;
    if (tp < 0) { dw = a;      dc = c; }
    else        { dw = a ^ 1u; dc = (unsigned)g_nt[a ^ 1u][tp]; }

    const float4* __restrict__ src = a ? x2 : x1;
    unsigned s4 = ((row & 4095u) << 10) + (unsigned)t;
    unsigned d4 = (((((dw << 3) + b) << 9) + dc) << 10) + (unsigned)t;

    float4 v0 = __ldcs(src + s4);
    float4 v1 = __ldcs(src + s4 + 256);
    float4 v2 = __ldcs(src + s4 + 512);
    float4 v3 = __ldcs(src + s4 + 768);
    __stcs(out + d4,       v0);
    __stcs(out + d4 + 256, v1);
    __stcs(out + d4 + 512, v2);
    __stcs(out + d4 + 768, v3);

    // ─── Reset handshake for the next graph replay (last block only). ───
    if (t == 0) {
        int d = atomicAdd(&g_done, 1);
        if (d == (int)ROWS - 1) {
            g_done = 0;
            g_ready = 0;
            g_tab = 0;
        }
    }
}

extern "C" void kernel_launch(void* const* d_in, const int* in_sizes, int n_in,
                              void* d_out, int out_size) {
    const float* x1  = (const float*)d_in[0];
    const float* x2  = (const float*)d_in[1];
    const float* bn1 = (const float*)d_in[2];
    const float* bn2 = (const float*)d_in[3];

    exchange_fused_kernel<<<ROWS, 256>>>((const float4*)x1,
                                         (const float4*)x2,
                                         (float4*)d_out,
                                         bn1, bn2);
}